// round 14
// baseline (speedup 1.0000x reference)
#include <cuda_runtime.h>
#include <math.h>

#define BATCH 16
#define ENCN  64
#define HDIM  96
#define EDIM  128
#define VOC   32000

typedef unsigned long long u64;

__device__ __forceinline__ u64 pack2(float x) {
    u64 r;
    asm("mov.b64 %0, {%1, %1};" : "=l"(r) : "r"(__float_as_uint(x)));
    return r;
}
__device__ __forceinline__ u64 fma2(u64 a, u64 b, u64 c) {
    u64 d;
    asm("fma.rn.f32x2 %0, %1, %2, %3;" : "=l"(d) : "l"(a), "l"(b), "l"(c));
    return d;
}
__device__ __forceinline__ void unpack2(u64 v, float& lo, float& hi) {
    unsigned int l, h;
    asm("mov.b64 {%0, %1}, %2;" : "=r"(l), "=r"(h) : "l"(v));
    lo = __uint_as_float(l);
    hi = __uint_as_float(h);
}

// ---------------- scratch ----------------
__device__ float g_efp[4][BATCH * ENCN * HDIM];  // enc_feat partials (16 i each; +bias in [0])
__device__ float g_o[BATCH * HDIM];
__device__ float g_psum[BATCH * 256];            // [b][block]

// =====================================================================
// K1: enc_feat, transposed mapping: warp = one i-channel, lanes = w.
// Out[o,w] += sum_d K[o,i,d] * Epad[i][w+d]
// grid (16 b, 8 og, 4 ichunk); block 128 = 4 warps (each warp: 4 i's).
// Per warp: 4 o-pairs in registers (acc[4][3] f32x2).
// K LDS.64 = warp-broadcast (1 wavefront, conflict-free by construction);
// E pre-duplicated as (e,e) u64, lane-consecutive loads (conflict-free).
// Inner loop per d: 3 LDS.64(E) + 4 LDS.64(K) + 12 fma2.
// =====================================================================
extern __shared__ u64 smem1[];

__global__ void __launch_bounds__(128)
enc_feat_kernel(const float* __restrict__ enc,
                const float* __restrict__ attn_w,
                const float* __restrict__ attn_b) {
    int b  = blockIdx.x;        // 16
    int og = blockIdx.y;        // 8 -> o-pairs og*4..og*4+3 (o = og*8..og*8+7)
    int ic = blockIdx.z;        // 4 -> i = ic*16..ic*16+15

    u64* sEd = smem1;                 // [16][192] (e,e) duplicated, zero-padded (24KB)
    u64* sKd = smem1 + 16 * 192;      // [4 op][16 i][96 d] (k_even, k_odd)   (48KB)

    int t    = threadIdx.x;     // 128
    int lane = t & 31;
    int wid  = t >> 5;          // 4 warps

    // zero padded E
    for (int idx = t; idx < 16 * 192; idx += 128) sEd[idx] = 0ull;
    __syncthreads();
    // fill E duplicated
    for (int idx = t; idx < 16 * 96; idx += 128) {
        int i = idx / 96, x = idx - i * 96;
        sEd[i * 192 + 47 + x] = pack2(enc[(b * 64 + ic * 16 + i) * 96 + x]);
    }
    // fill K pairs: attn_w[o*589824 + i*9216 + 47*96 + d]
    for (int idx = t; idx < 4 * 16 * 96; idx += 128) {
        int op = idx / 1536;
        int r  = idx - op * 1536;
        int i  = r / 96, d = r - i * 96;
        const float* kp = attn_w + (size_t)(og * 8 + op * 2) * 589824
                                 + (size_t)(ic * 16 + i) * 9216 + 4512 + d;
        float2 kk = make_float2(kp[0], kp[589824]);
        sKd[idx] = *(u64*)&kk;
    }
    __syncthreads();

    u64 acc[4][3];
#pragma unroll
    for (int p = 0; p < 4; p++)
#pragma unroll
        for (int r = 0; r < 3; r++) acc[p][r] = 0ull;

#pragma unroll 1
    for (int ii = 0; ii < 4; ii++) {
        int i = wid * 4 + ii;
        const u64* Ed = sEd + i * 192 + lane;
        const u64* K0 = sKd + (0 * 16 + i) * 96;
        const u64* K1 = sKd + (1 * 16 + i) * 96;
        const u64* K2 = sKd + (2 * 16 + i) * 96;
        const u64* K3 = sKd + (3 * 16 + i) * 96;
#pragma unroll 4
        for (int d = 0; d < 96; d++) {
            u64 e0 = Ed[d];
            u64 e1 = Ed[d + 32];
            u64 e2 = Ed[d + 64];
            u64 ka = K0[d], kb = K1[d], kc = K2[d], kd = K3[d];
            acc[0][0] = fma2(e0, ka, acc[0][0]);
            acc[0][1] = fma2(e1, ka, acc[0][1]);
            acc[0][2] = fma2(e2, ka, acc[0][2]);
            acc[1][0] = fma2(e0, kb, acc[1][0]);
            acc[1][1] = fma2(e1, kb, acc[1][1]);
            acc[1][2] = fma2(e2, kb, acc[1][2]);
            acc[2][0] = fma2(e0, kc, acc[2][0]);
            acc[2][1] = fma2(e1, kc, acc[2][1]);
            acc[2][2] = fma2(e2, kc, acc[2][2]);
            acc[3][0] = fma2(e0, kd, acc[3][0]);
            acc[3][1] = fma2(e1, kd, acc[3][1]);
            acc[3][2] = fma2(e2, kd, acc[3][2]);
        }
    }

    // inter-warp reduction over the 4 i-subsets
    __syncthreads();
    float* buf = (float*)sEd;       // 4 warps x 768 floats = 12KB (fits in sEd area)
#pragma unroll
    for (int p = 0; p < 4; p++)
#pragma unroll
        for (int r = 0; r < 3; r++) {
            float lo, hi;
            unpack2(acc[p][r], lo, hi);
            buf[wid * 768 + p * 192 + lane + 32 * r]      = lo;
            buf[wid * 768 + p * 192 + 96 + lane + 32 * r] = hi;
        }
    __syncthreads();

    float* dst = g_efp[ic];
    for (int idx = t; idx < 768; idx += 128) {
        float s = (buf[idx] + buf[768 + idx]) + (buf[1536 + idx] + buf[2304 + idx]);
        int p  = idx / 192;
        int rm = idx - p * 192;
        int eo = rm / 96;
        int w  = rm - eo * 96;
        int o  = og * 8 + p * 2 + eo;
        if (ic == 0) s += attn_b[o];
        dst[(b * 64 + o) * 96 + w] = s;
    }
}

// =====================================================================
// K2: fully fused per-batch decoder: attn1 -> GRU -> attn2 -> outproj.
// grid=16 (one block per batch), block=1024 (32 warps).
// =====================================================================
extern __shared__ float smem2[];

__global__ void decoder_fused_kernel(const float* __restrict__ enc,
                                     const int* __restrict__ ids,
                                     const float* __restrict__ hidden,
                                     const float* __restrict__ coverage,
                                     const float* __restrict__ emb,
                                     const float* __restrict__ W_dec,
                                     const float* __restrict__ b_dec,
                                     const float* __restrict__ cvg_w,
                                     const float* __restrict__ cvg_b,
                                     const float* __restrict__ v,
                                     const float* __restrict__ W_new,
                                     const float* __restrict__ b_new,
                                     const float* __restrict__ w_ih,
                                     const float* __restrict__ w_hh,
                                     const float* __restrict__ b_ih,
                                     const float* __restrict__ b_hh,
                                     const float* __restrict__ W_pre,
                                     const float* __restrict__ b_pre,
                                     float* __restrict__ out_hidden,
                                     float* __restrict__ out_ctx2,
                                     float* __restrict__ out_aw2,
                                     float* __restrict__ out_cov2) {
    int b    = blockIdx.x;
    int t    = threadIdx.x;     // 1024
    int warp = t >> 5;
    int lane = t & 31;

    float* sWdec = smem2;               // 9216
    float* sC    = sWdec + 9216;        // 4096   C[e][i] = cvg_w[e,i,0,47]
    float* sEnc  = sC + 4096;           // 6144   enc[b]
    float* sEf   = sEnc + 6144;         // 6144   encfeat[b]

    __shared__ float sh[96], sv[96], scov[64], sdec[96], scvg[64], ss[64],
                     saw[64], sred[64], sctx[96], scat[224], sx[96],
                     sgi[288], sgh[288], shnew[96], so2[192];

    for (int i = t; i < 9216; i += 1024) sWdec[i] = W_dec[i];
    for (int i = t; i < 4096; i += 1024) {
        int e = i >> 6, ii = i & 63;
        sC[i] = cvg_w[e * 6144 + ii * 96 + 47];
    }
    for (int i = t; i < 6144; i += 1024) {
        sEnc[i] = enc[b * 6144 + i];
        sEf[i]  = (g_efp[0][b * 6144 + i] + g_efp[1][b * 6144 + i])
                + (g_efp[2][b * 6144 + i] + g_efp[3][b * 6144 + i]);
    }
    if (t < 96) { sh[t] = hidden[b * 96 + t]; sv[t] = v[b * 96 + t]; }
    if (t < 64) scov[t] = coverage[b * 64 + t];
    __syncthreads();

    // =========== PHASE A: attention #1 ===========
#pragma unroll
    for (int k = 0; k < 3; k++) {
        int h = warp * 3 + k;
        const float* wr = sWdec + h * 96;
        float a = sh[lane] * wr[lane];
        a = fmaf(sh[lane + 32], wr[lane + 32], a);
        a = fmaf(sh[lane + 64], wr[lane + 64], a);
#pragma unroll
        for (int s = 16; s > 0; s >>= 1) a += __shfl_down_sync(0xffffffffu, a, s);
        if (lane == 0) sdec[h] = a + b_dec[h];
    }
#pragma unroll
    for (int k = 0; k < 2; k++) {
        int e = warp * 2 + k;
        const float* cw = sC + e * 64;
        float c = scov[lane] * cw[lane];
        c = fmaf(scov[lane + 32], cw[lane + 32], c);
#pragma unroll
        for (int s = 16; s > 0; s >>= 1) c += __shfl_down_sync(0xffffffffu, c, s);
        if (lane == 0) scvg[e] = c + cvg_b[e];
    }
    __syncthreads();

#pragma unroll
    for (int k = 0; k < 2; k++) {
        int e = warp * 2 + k;
        const float* ef = sEf + e * 96;
        float cg = scvg[e];
        float a = 0.f;
#pragma unroll
        for (int q = 0; q < 3; q++) {
            int h = lane + 32 * q;
            a = fmaf(tanhf(ef[h] + sdec[h] + cg), sv[h], a);
        }
#pragma unroll
        for (int s = 16; s > 0; s >>= 1) a += __shfl_down_sync(0xffffffffu, a, s);
        if (lane == 0) ss[e] = a;
    }
    __syncthreads();

    float ex = 0.f;
    if (t < 64) {
        float m = -1e30f;
#pragma unroll
        for (int e = 0; e < 64; e++) m = fmaxf(m, ss[e]);
        ex = expf(ss[t] - m);
        sred[t] = ex;
    }
    __syncthreads();
    for (int s = 32; s >= 1; s >>= 1) {
        if (t < s) sred[t] += sred[t + s];
        __syncthreads();
    }
    {
        float invZ = 1.0f / sred[0];
        if (t < 64) {
            float aw = ex * invZ;
            saw[t] = aw;
            scov[t] = scov[t] + aw;
        }
    }
    __syncthreads();

    if (t < 96) {
        float c = 0.f;
        const float* ebp = sEnc + t;
#pragma unroll 8
        for (int e = 0; e < 64; e++) c = fmaf(saw[e], ebp[e * 96], c);
        sctx[t] = c;
    }
    __syncthreads();

    // =========== GRU ===========
    {
        int id = ids[b];
        if (t < 224) scat[t] = (t < 128) ? emb[(size_t)id * 128 + t] : sctx[t - 128];
    }
    __syncthreads();

#pragma unroll
    for (int k = 0; k < 3; k++) {
        int h = warp * 3 + k;
        const float* wr = W_new + h * 224;
        float a = 0.f;
#pragma unroll
        for (int q = 0; q < 7; q++) {
            int j = lane + 32 * q;
            a = fmaf(scat[j], wr[j], a);
        }
#pragma unroll
        for (int s = 16; s > 0; s >>= 1) a += __shfl_down_sync(0xffffffffu, a, s);
        if (lane == 0) sx[h] = a + b_new[h];
    }
    __syncthreads();

#pragma unroll
    for (int k = 0; k < 18; k++) {
        int r = k * 32 + warp;
        bool is_gi = r < 288;
        int rr = is_gi ? r : r - 288;
        const float* wr  = (is_gi ? w_ih : w_hh) + rr * 96;
        const float* vec = is_gi ? sx : sh;
        float a = vec[lane] * wr[lane];
        a = fmaf(vec[lane + 32], wr[lane + 32], a);
        a = fmaf(vec[lane + 64], wr[lane + 64], a);
#pragma unroll
        for (int s = 16; s > 0; s >>= 1) a += __shfl_down_sync(0xffffffffu, a, s);
        if (lane == 0) {
            if (is_gi) sgi[rr] = a + b_ih[rr];
            else       sgh[rr] = a + b_hh[rr];
        }
    }
    __syncthreads();

    if (t < 96) {
        float r = 1.0f / (1.0f + expf(-(sgi[t] + sgh[t])));
        float z = 1.0f / (1.0f + expf(-(sgi[96 + t] + sgh[96 + t])));
        float n = tanhf(sgi[192 + t] + r * sgh[192 + t]);
        float hn = (1.0f - z) * n + z * sh[t];
        shnew[t] = hn;
        out_hidden[b * 96 + t] = hn;
    }
    __syncthreads();

    // =========== PHASE B: attention #2 ===========
#pragma unroll
    for (int k = 0; k < 3; k++) {
        int h = warp * 3 + k;
        const float* wr = sWdec + h * 96;
        float a = shnew[lane] * wr[lane];
        a = fmaf(shnew[lane + 32], wr[lane + 32], a);
        a = fmaf(shnew[lane + 64], wr[lane + 64], a);
#pragma unroll
        for (int s = 16; s > 0; s >>= 1) a += __shfl_down_sync(0xffffffffu, a, s);
        if (lane == 0) sdec[h] = a + b_dec[h];
    }
#pragma unroll
    for (int k = 0; k < 2; k++) {
        int e = warp * 2 + k;
        const float* cw = sC + e * 64;
        float c = scov[lane] * cw[lane];
        c = fmaf(scov[lane + 32], cw[lane + 32], c);
#pragma unroll
        for (int s = 16; s > 0; s >>= 1) c += __shfl_down_sync(0xffffffffu, c, s);
        if (lane == 0) scvg[e] = c + cvg_b[e];
    }
    __syncthreads();

#pragma unroll
    for (int k = 0; k < 2; k++) {
        int e = warp * 2 + k;
        const float* ef = sEf + e * 96;
        float cg = scvg[e];
        float a = 0.f;
#pragma unroll
        for (int q = 0; q < 3; q++) {
            int h = lane + 32 * q;
            a = fmaf(tanhf(ef[h] + sdec[h] + cg), sv[h], a);
        }
#pragma unroll
        for (int s = 16; s > 0; s >>= 1) a += __shfl_down_sync(0xffffffffu, a, s);
        if (lane == 0) ss[e] = a;
    }
    __syncthreads();

    ex = 0.f;
    if (t < 64) {
        float m = -1e30f;
#pragma unroll
        for (int e = 0; e < 64; e++) m = fmaxf(m, ss[e]);
        ex = expf(ss[t] - m);
        sred[t] = ex;
    }
    __syncthreads();
    for (int s = 32; s >= 1; s >>= 1) {
        if (t < s) sred[t] += sred[t + s];
        __syncthreads();
    }
    {
        float invZ = 1.0f / sred[0];
        if (t < 64) {
            float aw = ex * invZ;
            saw[t] = aw;
            out_aw2[b * 64 + t]  = aw;
            out_cov2[b * 64 + t] = scov[t] + aw;
        }
    }
    __syncthreads();

    if (t < 96) {
        float c = 0.f;
        const float* ebp = sEnc + t;
#pragma unroll 8
        for (int e = 0; e < 64; e++) c = fmaf(saw[e], ebp[e * 96], c);
        out_ctx2[b * 96 + t] = c;
        so2[t]       = shnew[t];
        so2[96 + t]  = c;
    }
    __syncthreads();

    // =========== outproj ===========
#pragma unroll
    for (int k = 0; k < 3; k++) {
        int h = warp * 3 + k;
        const float* wr = W_pre + h * 192;
        float a = 0.f;
#pragma unroll
        for (int q = 0; q < 6; q++) {
            int j = lane + 32 * q;
            a = fmaf(so2[j], wr[j], a);
        }
#pragma unroll
        for (int s = 16; s > 0; s >>= 1) a += __shfl_down_sync(0xffffffffu, a, s);
        if (lane == 0) g_o[b * 96 + h] = tanhf(a + b_pre[h]);
    }
}

// =====================================================================
// K3: logits via f32x2, coalesced smem-staged W (R7 design).
// 250 blocks x 128 threads; psum stored b-major.
// =====================================================================
extern __shared__ float smem3[];

__global__ void logits_kernel(const float* __restrict__ W_out,
                              const float* __restrict__ b_out,
                              float* __restrict__ out_logp) {
    float* sW = smem3;                               // 128 * 97 (padded)
    __shared__ __align__(16) u64 sO2[96 * 8];        // [k][bpair]
    __shared__ float swred[4][16];
    int t = threadIdx.x;        // 128
    int warp = t >> 5, lane = t & 31;
    int v0 = blockIdx.x * 128;

    {
        const float4* src = (const float4*)(W_out + (size_t)v0 * 96);
        for (int idx = t; idx < 128 * 24; idx += 128) {
            int r = idx / 24;
            int k4 = idx - r * 24;
            float4 w4 = src[r * 24 + k4];
            float* dst = sW + r * 97 + k4 * 4;
            dst[0] = w4.x; dst[1] = w4.y; dst[2] = w4.z; dst[3] = w4.w;
        }
    }
    for (int idx = t; idx < 96 * 8; idx += 128) {
        int k = idx >> 3, q = idx & 7;
        float2 oo = make_float2(g_o[(2 * q) * 96 + k], g_o[(2 * q + 1) * 96 + k]);
        sO2[idx] = *(u64*)&oo;
    }
    __syncthreads();

    u64 acc2[8] = {0ull, 0ull, 0ull, 0ull, 0ull, 0ull, 0ull, 0ull};
    const float* wr = sW + t * 97;
#pragma unroll 4
    for (int k = 0; k < 96; k++) {
        u64 wp = pack2(wr[k]);
        const u64* o2 = sO2 + k * 8;
#pragma unroll
        for (int q = 0; q < 8; q++) acc2[q] = fma2(wp, o2[q], acc2[q]);
    }

    float acc[16];
#pragma unroll
    for (int q = 0; q < 8; q++) unpack2(acc2[q], acc[2 * q], acc[2 * q + 1]);

    float bo = b_out[v0 + t];
#pragma unroll
    for (int bb = 0; bb < 16; bb++) {
        acc[bb] += bo;
        out_logp[bb * VOC + v0 + t] = acc[bb];
        acc[bb] = expf(acc[bb]);
    }
#pragma unroll
    for (int bb = 0; bb < 16; bb++) {
#pragma unroll
        for (int s = 16; s > 0; s >>= 1) acc[bb] += __shfl_down_sync(0xffffffffu, acc[bb], s);
    }
    if (lane == 0) {
#pragma unroll
        for (int bb = 0; bb < 16; bb++) swred[warp][bb] = acc[bb];
    }
    __syncthreads();
    if (t < 16) {
        float s = swred[0][t] + swred[1][t] + swred[2][t] + swred[3][t];
        g_psum[t * 256 + blockIdx.x] = s;       // b-major
    }
}

// =====================================================================
// K4: finalize. Payload loaded first, overlapped logZ.
// grid (32, 16), block 256.
// =====================================================================
__global__ void finalize_kernel(float* __restrict__ out_logp) {
    int b = blockIdx.y;
    int t = threadIdx.x;        // 256
    int lane = t & 31;

    float4* p = (float4*)(out_logp + (size_t)b * VOC) + blockIdx.x * 250;
    bool act = t < 250;
    float4 v = make_float4(0.f, 0.f, 0.f, 0.f);
    if (act) v = p[t];

    float s = 0.f;
    const float* ps = g_psum + b * 256;
#pragma unroll
    for (int q = 0; q < 8; q++) {
        int idx = q * 32 + lane;
        if (idx < 250) s += ps[idx];
    }
#pragma unroll
    for (int k = 16; k > 0; k >>= 1) s += __shfl_xor_sync(0xffffffffu, s, k);
    float lz = (lane == 0) ? logf(s) : 0.f;
    lz = __shfl_sync(0xffffffffu, lz, 0);

    if (act) {
        v.x -= lz; v.y -= lz; v.z -= lz; v.w -= lz;
        p[t] = v;
    }
}

// =====================================================================
extern "C" void kernel_launch(void* const* d_in, const int* in_sizes, int n_in,
                              void* d_out, int out_size) {
    const float* enc      = (const float*)d_in[0];
    const int*   ids      = (const int*)d_in[1];
    const float* hidden   = (const float*)d_in[2];
    const float* coverage = (const float*)d_in[3];
    const float* emb      = (const float*)d_in[4];
    const float* W_dec    = (const float*)d_in[5];
    const float* b_dec    = (const float*)d_in[6];
    const float* attn_w   = (const float*)d_in[7];
    const float* attn_b   = (const float*)d_in[8];
    const float* cvg_w    = (const float*)d_in[9];
    const float* cvg_b    = (const float*)d_in[10];
    const float* v        = (const float*)d_in[11];
    const float* W_new    = (const float*)d_in[12];
    const float* b_new    = (const float*)d_in[13];
    const float* w_ih     = (const float*)d_in[14];
    const float* w_hh     = (const float*)d_in[15];
    const float* b_ih     = (const float*)d_in[16];
    const float* b_hh     = (const float*)d_in[17];
    const float* W_pre    = (const float*)d_in[18];
    const float* b_pre    = (const float*)d_in[19];
    const float* W_out    = (const float*)d_in[20];
    const float* b_out    = (const float*)d_in[21];

    float* out        = (float*)d_out;
    float* out_logp   = out;                       // 16*32000
    float* out_hidden = out + 512000;              // 1*16*96
    float* out_ctx2   = out + 513536;              // 16*96
    float* out_aw2    = out + 515072;              // 16*64
    float* out_cov2   = out + 516096;              // 16*64

    int smem_k1 = (16 * 192 + 4 * 16 * 96) * 8;    // 24576 + 49152 = 73728 B
    cudaFuncSetAttribute(enc_feat_kernel, cudaFuncAttributeMaxDynamicSharedMemorySize, smem_k1);
    cudaFuncSetAttribute(decoder_fused_kernel, cudaFuncAttributeMaxDynamicSharedMemorySize, 25600 * 4);
    cudaFuncSetAttribute(logits_kernel, cudaFuncAttributeMaxDynamicSharedMemorySize, 128 * 97 * 4);

    // K1: enc_feat partials (transposed warp-lane mapping, conflict-free)
    enc_feat_kernel<<<dim3(16, 8, 4), 128, smem_k1>>>(enc, attn_w, attn_b);
    // K2: fused attn1 + GRU + attn2 + outproj (sums 4 partials)
    decoder_fused_kernel<<<16, 1024, 25600 * 4>>>(
        enc, ids, hidden, coverage, emb, W_dec, b_dec, cvg_w, cvg_b, v,
        W_new, b_new, w_ih, w_hh, b_ih, b_hh, W_pre, b_pre,
        out_hidden, out_ctx2, out_aw2, out_cov2);
    // K3: logits (coalesced smem-staged f32x2) + b-major sumexp partials
    logits_kernel<<<250, 128, 128 * 97 * 4>>>(W_out, b_out, out_logp);
    // K4: overlapped logZ + in-place normalize
    finalize_kernel<<<dim3(32, 16), 256>>>(out_logp);
}

// round 15
// speedup vs baseline: 1.2071x; 1.2071x over previous
#include <cuda_runtime.h>
#include <math.h>

#define BATCH 16
#define ENCN  64
#define HDIM  96
#define EDIM  128
#define VOC   32000

typedef unsigned long long u64;

__device__ __forceinline__ u64 pack2(float x) {
    u64 r;
    asm("mov.b64 %0, {%1, %1};" : "=l"(r) : "r"(__float_as_uint(x)));
    return r;
}
__device__ __forceinline__ u64 fma2(u64 a, u64 b, u64 c) {
    u64 d;
    asm("fma.rn.f32x2 %0, %1, %2, %3;" : "=l"(d) : "l"(a), "l"(b), "l"(c));
    return d;
}
__device__ __forceinline__ void unpack2(u64 v, float& lo, float& hi) {
    unsigned int l, h;
    asm("mov.b64 {%0, %1}, %2;" : "=r"(l), "=r"(h) : "l"(v));
    lo = __uint_as_float(l);
    hi = __uint_as_float(h);
}

// ---------------- scratch ----------------
__device__ float g_ef0[BATCH * ENCN * HDIM];   // enc_feat partial (i 0..31, +bias)
__device__ float g_ef1[BATCH * ENCN * HDIM];   // enc_feat partial (i 32..63)
__device__ float g_o[BATCH * HDIM];
__device__ float g_psum[BATCH * 256];          // [b][block]

// =====================================================================
// K1: enc_feat partials, o-QUAD blocks (R7 inner loop, 2 o-pairs/block).
// grid (16b * 16og, 2 i-half); block 128 = 16 i-groups (2 ch) x 8 w-thr.
// Per u-step: 2 LDS.64(K) + 1 E slide + 24 fma.rn.f32x2 (ratio 1.17).
// 72KB smem -> 3 blocks/SM -> 444 resident vs 512 blocks = 1.15 waves.
// =====================================================================
extern __shared__ float smem1[];

__global__ void __launch_bounds__(128)
enc_feat_kernel(const float* __restrict__ enc,
                const float* __restrict__ attn_w,
                const float* __restrict__ attn_b) {
    int bx   = blockIdx.x;          // 256 = b*16 + og
    int b    = bx >> 4;
    int og   = bx & 15;             // o-quad: o = og*4 .. og*4+3
    int half = blockIdx.y;
    int i0   = half * 32;

    float* sE  = smem1;                         // 32 * 192 floats (24KB)
    u64*   sKa = (u64*)(smem1 + 32 * 192);      // 32 * 96 packed (o0, o1) (24KB)
    u64*   sKb = sKa + 32 * 96;                 // 32 * 96 packed (o2, o3) (24KB)
    int tid = threadIdx.x;          // 128

    float4* sE4 = (float4*)sE;
    for (int i = tid; i < 32 * 192 / 4; i += 128) sE4[i] = make_float4(0.f, 0.f, 0.f, 0.f);
    __syncthreads();

    const float* eb = enc + (b * ENCN + i0) * HDIM;
    for (int idx = tid; idx < 32 * HDIM; idx += 128) {
        int i = idx / 96;
        int x = idx - i * 96;
        sE[i * 192 + 47 + x] = eb[idx];
    }
    // K staging for 4 o's (two pairs)
    {
        const float* kq = attn_w + (size_t)(og * 4) * 589824 + (size_t)i0 * 9216 + 4512;
        for (int idx = tid; idx < 2 * 32 * 96; idx += 128) {
            int pair = idx / 3072;
            int r    = idx - pair * 3072;
            int i    = r / 96, d = r - i * 96;
            const float* kp = kq + (size_t)(pair * 2) * 589824 + (size_t)i * 9216 + d;
            float2 kk = make_float2(kp[0], kp[589824]);
            (pair ? sKb : sKa)[i * 96 + d] = *(u64*)&kk;
        }
    }
    __syncthreads();

    int ig = tid >> 3;      // 0..15, 2 channels each
    int wt = tid & 7;       // 0..7
    int w0 = wt * 12;

    u64 accA[12], accB[12];
#pragma unroll
    for (int j = 0; j < 12; j++) { accA[j] = 0ull; accB[j] = 0ull; }

#pragma unroll 1
    for (int i = ig * 2; i < ig * 2 + 2; i++) {
        const float* Er = sE + i * 192 + w0;
        const u64*   Ka = sKa + i * 96;
        const u64*   Kb = sKb + i * 96;
        u64 ep[12];
#pragma unroll
        for (int j = 0; j < 12; j++) ep[j] = pack2(Er[j]);
#pragma unroll 1
        for (int d = 0; d < 96; d += 12) {
#pragma unroll
            for (int u = 0; u < 12; u++) {
                u64 ka = Ka[d + u];
                u64 kb = Kb[d + u];
#pragma unroll
                for (int j = 0; j < 12; j++) {
                    u64 ev = ep[(u + j) % 12];       // static idx after unroll
                    accA[j] = fma2(ev, ka, accA[j]);
                    accB[j] = fma2(ev, kb, accB[j]);
                }
                ep[u] = pack2(Er[d + u + 12]);       // slide (max idx 6143, in-bounds)
            }
        }
    }

    // unpack: accA -> o0,o1 ; accB -> o2,o3
    float a0[12], a1[12], a2[12], a3[12];
#pragma unroll
    for (int j = 0; j < 12; j++) {
        unpack2(accA[j], a0[j], a1[j]);
        unpack2(accB[j], a2[j], a3[j]);
    }

    // reduce the 16 i-groups (tree over tid strides 64,32,16,8)
    __syncthreads();
    float* red = smem1;     // reuse (128 * 48 floats = 24 KB, fits sE region)
#pragma unroll
    for (int j = 0; j < 12; j++) {
        red[tid * 48 + j]      = a0[j];
        red[tid * 48 + 12 + j] = a1[j];
        red[tid * 48 + 24 + j] = a2[j];
        red[tid * 48 + 36 + j] = a3[j];
    }
    __syncthreads();
    for (int s = 64; s >= 8; s >>= 1) {
        if (tid < s) {
#pragma unroll
            for (int j = 0; j < 48; j++) red[tid * 48 + j] += red[(tid + s) * 48 + j];
        }
        __syncthreads();
    }
    if (tid < 8) {
        float* dst = half ? g_ef1 : g_ef0;
#pragma unroll
        for (int r = 0; r < 4; r++) {
            int o = og * 4 + r;
            float bb = half ? 0.f : attn_b[o];
#pragma unroll
            for (int j = 0; j < 12; j++) {
                dst[(b * ENCN + o) * 96 + tid * 12 + j] = red[tid * 48 + r * 12 + j] + bb;
            }
        }
    }
}

// =====================================================================
// K2: fully fused per-batch decoder: attn1 -> GRU -> attn2 -> outproj.
// grid=16 (one block per batch), block=1024 (32 warps).
// =====================================================================
extern __shared__ float smem2[];

__global__ void decoder_fused_kernel(const float* __restrict__ enc,
                                     const int* __restrict__ ids,
                                     const float* __restrict__ hidden,
                                     const float* __restrict__ coverage,
                                     const float* __restrict__ emb,
                                     const float* __restrict__ W_dec,
                                     const float* __restrict__ b_dec,
                                     const float* __restrict__ cvg_w,
                                     const float* __restrict__ cvg_b,
                                     const float* __restrict__ v,
                                     const float* __restrict__ W_new,
                                     const float* __restrict__ b_new,
                                     const float* __restrict__ w_ih,
                                     const float* __restrict__ w_hh,
                                     const float* __restrict__ b_ih,
                                     const float* __restrict__ b_hh,
                                     const float* __restrict__ W_pre,
                                     const float* __restrict__ b_pre,
                                     float* __restrict__ out_hidden,
                                     float* __restrict__ out_ctx2,
                                     float* __restrict__ out_aw2,
                                     float* __restrict__ out_cov2) {
    int b    = blockIdx.x;
    int t    = threadIdx.x;     // 1024
    int warp = t >> 5;
    int lane = t & 31;

    float* sWdec = smem2;               // 9216
    float* sC    = sWdec + 9216;        // 4096   C[e][i] = cvg_w[e,i,0,47]
    float* sEnc  = sC + 4096;           // 6144   enc[b]
    float* sEf   = sEnc + 6144;         // 6144   encfeat[b]

    __shared__ float sh[96], sv[96], scov[64], sdec[96], scvg[64], ss[64],
                     saw[64], sred[64], sctx[96], scat[224], sx[96],
                     sgi[288], sgh[288], shnew[96], so2[192];

    for (int i = t; i < 9216; i += 1024) sWdec[i] = W_dec[i];
    for (int i = t; i < 4096; i += 1024) {
        int e = i >> 6, ii = i & 63;
        sC[i] = cvg_w[e * 6144 + ii * 96 + 47];
    }
    for (int i = t; i < 6144; i += 1024) {
        sEnc[i] = enc[b * 6144 + i];
        sEf[i]  = g_ef0[b * 6144 + i] + g_ef1[b * 6144 + i];
    }
    if (t < 96) { sh[t] = hidden[b * 96 + t]; sv[t] = v[b * 96 + t]; }
    if (t < 64) scov[t] = coverage[b * 64 + t];
    __syncthreads();

    // =========== PHASE A: attention #1 ===========
#pragma unroll
    for (int k = 0; k < 3; k++) {
        int h = warp * 3 + k;
        const float* wr = sWdec + h * 96;
        float a = sh[lane] * wr[lane];
        a = fmaf(sh[lane + 32], wr[lane + 32], a);
        a = fmaf(sh[lane + 64], wr[lane + 64], a);
#pragma unroll
        for (int s = 16; s > 0; s >>= 1) a += __shfl_down_sync(0xffffffffu, a, s);
        if (lane == 0) sdec[h] = a + b_dec[h];
    }
#pragma unroll
    for (int k = 0; k < 2; k++) {
        int e = warp * 2 + k;
        const float* cw = sC + e * 64;
        float c = scov[lane] * cw[lane];
        c = fmaf(scov[lane + 32], cw[lane + 32], c);
#pragma unroll
        for (int s = 16; s > 0; s >>= 1) c += __shfl_down_sync(0xffffffffu, c, s);
        if (lane == 0) scvg[e] = c + cvg_b[e];
    }
    __syncthreads();

#pragma unroll
    for (int k = 0; k < 2; k++) {
        int e = warp * 2 + k;
        const float* ef = sEf + e * 96;
        float cg = scvg[e];
        float a = 0.f;
#pragma unroll
        for (int q = 0; q < 3; q++) {
            int h = lane + 32 * q;
            a = fmaf(tanhf(ef[h] + sdec[h] + cg), sv[h], a);
        }
#pragma unroll
        for (int s = 16; s > 0; s >>= 1) a += __shfl_down_sync(0xffffffffu, a, s);
        if (lane == 0) ss[e] = a;
    }
    __syncthreads();

    float ex = 0.f;
    if (t < 64) {
        float m = -1e30f;
#pragma unroll
        for (int e = 0; e < 64; e++) m = fmaxf(m, ss[e]);
        ex = expf(ss[t] - m);
        sred[t] = ex;
    }
    __syncthreads();
    for (int s = 32; s >= 1; s >>= 1) {
        if (t < s) sred[t] += sred[t + s];
        __syncthreads();
    }
    {
        float invZ = 1.0f / sred[0];
        if (t < 64) {
            float aw = ex * invZ;
            saw[t] = aw;
            scov[t] = scov[t] + aw;
        }
    }
    __syncthreads();

    if (t < 96) {
        float c = 0.f;
        const float* ebp = sEnc + t;
#pragma unroll 8
        for (int e = 0; e < 64; e++) c = fmaf(saw[e], ebp[e * 96], c);
        sctx[t] = c;
    }
    __syncthreads();

    // =========== GRU ===========
    {
        int id = ids[b];
        if (t < 224) scat[t] = (t < 128) ? emb[(size_t)id * 128 + t] : sctx[t - 128];
    }
    __syncthreads();

#pragma unroll
    for (int k = 0; k < 3; k++) {
        int h = warp * 3 + k;
        const float* wr = W_new + h * 224;
        float a = 0.f;
#pragma unroll
        for (int q = 0; q < 7; q++) {
            int j = lane + 32 * q;
            a = fmaf(scat[j], wr[j], a);
        }
#pragma unroll
        for (int s = 16; s > 0; s >>= 1) a += __shfl_down_sync(0xffffffffu, a, s);
        if (lane == 0) sx[h] = a + b_new[h];
    }
    __syncthreads();

#pragma unroll
    for (int k = 0; k < 18; k++) {
        int r = k * 32 + warp;
        bool is_gi = r < 288;
        int rr = is_gi ? r : r - 288;
        const float* wr  = (is_gi ? w_ih : w_hh) + rr * 96;
        const float* vec = is_gi ? sx : sh;
        float a = vec[lane] * wr[lane];
        a = fmaf(vec[lane + 32], wr[lane + 32], a);
        a = fmaf(vec[lane + 64], wr[lane + 64], a);
#pragma unroll
        for (int s = 16; s > 0; s >>= 1) a += __shfl_down_sync(0xffffffffu, a, s);
        if (lane == 0) {
            if (is_gi) sgi[rr] = a + b_ih[rr];
            else       sgh[rr] = a + b_hh[rr];
        }
    }
    __syncthreads();

    if (t < 96) {
        float r = 1.0f / (1.0f + expf(-(sgi[t] + sgh[t])));
        float z = 1.0f / (1.0f + expf(-(sgi[96 + t] + sgh[96 + t])));
        float n = tanhf(sgi[192 + t] + r * sgh[192 + t]);
        float hn = (1.0f - z) * n + z * sh[t];
        shnew[t] = hn;
        out_hidden[b * 96 + t] = hn;
    }
    __syncthreads();

    // =========== PHASE B: attention #2 ===========
#pragma unroll
    for (int k = 0; k < 3; k++) {
        int h = warp * 3 + k;
        const float* wr = sWdec + h * 96;
        float a = shnew[lane] * wr[lane];
        a = fmaf(shnew[lane + 32], wr[lane + 32], a);
        a = fmaf(shnew[lane + 64], wr[lane + 64], a);
#pragma unroll
        for (int s = 16; s > 0; s >>= 1) a += __shfl_down_sync(0xffffffffu, a, s);
        if (lane == 0) sdec[h] = a + b_dec[h];
    }
#pragma unroll
    for (int k = 0; k < 2; k++) {
        int e = warp * 2 + k;
        const float* cw = sC + e * 64;
        float c = scov[lane] * cw[lane];
        c = fmaf(scov[lane + 32], cw[lane + 32], c);
#pragma unroll
        for (int s = 16; s > 0; s >>= 1) c += __shfl_down_sync(0xffffffffu, c, s);
        if (lane == 0) scvg[e] = c + cvg_b[e];
    }
    __syncthreads();

#pragma unroll
    for (int k = 0; k < 2; k++) {
        int e = warp * 2 + k;
        const float* ef = sEf + e * 96;
        float cg = scvg[e];
        float a = 0.f;
#pragma unroll
        for (int q = 0; q < 3; q++) {
            int h = lane + 32 * q;
            a = fmaf(tanhf(ef[h] + sdec[h] + cg), sv[h], a);
        }
#pragma unroll
        for (int s = 16; s > 0; s >>= 1) a += __shfl_down_sync(0xffffffffu, a, s);
        if (lane == 0) ss[e] = a;
    }
    __syncthreads();

    ex = 0.f;
    if (t < 64) {
        float m = -1e30f;
#pragma unroll
        for (int e = 0; e < 64; e++) m = fmaxf(m, ss[e]);
        ex = expf(ss[t] - m);
        sred[t] = ex;
    }
    __syncthreads();
    for (int s = 32; s >= 1; s >>= 1) {
        if (t < s) sred[t] += sred[t + s];
        __syncthreads();
    }
    {
        float invZ = 1.0f / sred[0];
        if (t < 64) {
            float aw = ex * invZ;
            saw[t] = aw;
            out_aw2[b * 64 + t]  = aw;
            out_cov2[b * 64 + t] = scov[t] + aw;
        }
    }
    __syncthreads();

    if (t < 96) {
        float c = 0.f;
        const float* ebp = sEnc + t;
#pragma unroll 8
        for (int e = 0; e < 64; e++) c = fmaf(saw[e], ebp[e * 96], c);
        out_ctx2[b * 96 + t] = c;
        so2[t]       = shnew[t];
        so2[96 + t]  = c;
    }
    __syncthreads();

    // =========== outproj ===========
#pragma unroll
    for (int k = 0; k < 3; k++) {
        int h = warp * 3 + k;
        const float* wr = W_pre + h * 192;
        float a = 0.f;
#pragma unroll
        for (int q = 0; q < 6; q++) {
            int j = lane + 32 * q;
            a = fmaf(so2[j], wr[j], a);
        }
#pragma unroll
        for (int s = 16; s > 0; s >>= 1) a += __shfl_down_sync(0xffffffffu, a, s);
        if (lane == 0) g_o[b * 96 + h] = tanhf(a + b_pre[h]);
    }
}

// =====================================================================
// K3: logits via f32x2, coalesced smem-staged W (R7 design).
// 250 blocks x 128 threads; psum stored b-major.
// =====================================================================
extern __shared__ float smem3[];

__global__ void logits_kernel(const float* __restrict__ W_out,
                              const float* __restrict__ b_out,
                              float* __restrict__ out_logp) {
    float* sW = smem3;                               // 128 * 97 (padded)
    __shared__ __align__(16) u64 sO2[96 * 8];        // [k][bpair]
    __shared__ float swred[4][16];
    int t = threadIdx.x;        // 128
    int warp = t >> 5, lane = t & 31;
    int v0 = blockIdx.x * 128;

    {
        const float4* src = (const float4*)(W_out + (size_t)v0 * 96);
        for (int idx = t; idx < 128 * 24; idx += 128) {
            int r = idx / 24;
            int k4 = idx - r * 24;
            float4 w4 = src[r * 24 + k4];
            float* dst = sW + r * 97 + k4 * 4;
            dst[0] = w4.x; dst[1] = w4.y; dst[2] = w4.z; dst[3] = w4.w;
        }
    }
    for (int idx = t; idx < 96 * 8; idx += 128) {
        int k = idx >> 3, q = idx & 7;
        float2 oo = make_float2(g_o[(2 * q) * 96 + k], g_o[(2 * q + 1) * 96 + k]);
        sO2[idx] = *(u64*)&oo;
    }
    __syncthreads();

    u64 acc2[8] = {0ull, 0ull, 0ull, 0ull, 0ull, 0ull, 0ull, 0ull};
    const float* wr = sW + t * 97;
#pragma unroll 4
    for (int k = 0; k < 96; k++) {
        u64 wp = pack2(wr[k]);
        const u64* o2 = sO2 + k * 8;
#pragma unroll
        for (int q = 0; q < 8; q++) acc2[q] = fma2(wp, o2[q], acc2[q]);
    }

    float acc[16];
#pragma unroll
    for (int q = 0; q < 8; q++) unpack2(acc2[q], acc[2 * q], acc[2 * q + 1]);

    float bo = b_out[v0 + t];
#pragma unroll
    for (int bb = 0; bb < 16; bb++) {
        acc[bb] += bo;
        out_logp[bb * VOC + v0 + t] = acc[bb];
        acc[bb] = expf(acc[bb]);
    }
#pragma unroll
    for (int bb = 0; bb < 16; bb++) {
#pragma unroll
        for (int s = 16; s > 0; s >>= 1) acc[bb] += __shfl_down_sync(0xffffffffu, acc[bb], s);
    }
    if (lane == 0) {
#pragma unroll
        for (int bb = 0; bb < 16; bb++) swred[warp][bb] = acc[bb];
    }
    __syncthreads();
    if (t < 16) {
        float s = swred[0][t] + swred[1][t] + swred[2][t] + swred[3][t];
        g_psum[t * 256 + blockIdx.x] = s;       // b-major
    }
}

// =====================================================================
// K4: finalize. Payload loaded first, overlapped logZ.
// grid (32, 16), block 256.
// =====================================================================
__global__ void finalize_kernel(float* __restrict__ out_logp) {
    int b = blockIdx.y;
    int t = threadIdx.x;        // 256
    int lane = t & 31;

    float4* p = (float4*)(out_logp + (size_t)b * VOC) + blockIdx.x * 250;
    bool act = t < 250;
    float4 v = make_float4(0.f, 0.f, 0.f, 0.f);
    if (act) v = p[t];

    float s = 0.f;
    const float* ps = g_psum + b * 256;
#pragma unroll
    for (int q = 0; q < 8; q++) {
        int idx = q * 32 + lane;
        if (idx < 250) s += ps[idx];
    }
#pragma unroll
    for (int k = 16; k > 0; k >>= 1) s += __shfl_xor_sync(0xffffffffu, s, k);
    float lz = (lane == 0) ? logf(s) : 0.f;
    lz = __shfl_sync(0xffffffffu, lz, 0);

    if (act) {
        v.x -= lz; v.y -= lz; v.z -= lz; v.w -= lz;
        p[t] = v;
    }
}

// =====================================================================
extern "C" void kernel_launch(void* const* d_in, const int* in_sizes, int n_in,
                              void* d_out, int out_size) {
    const float* enc      = (const float*)d_in[0];
    const int*   ids      = (const int*)d_in[1];
    const float* hidden   = (const float*)d_in[2];
    const float* coverage = (const float*)d_in[3];
    const float* emb      = (const float*)d_in[4];
    const float* W_dec    = (const float*)d_in[5];
    const float* b_dec    = (const float*)d_in[6];
    const float* attn_w   = (const float*)d_in[7];
    const float* attn_b   = (const float*)d_in[8];
    const float* cvg_w    = (const float*)d_in[9];
    const float* cvg_b    = (const float*)d_in[10];
    const float* v        = (const float*)d_in[11];
    const float* W_new    = (const float*)d_in[12];
    const float* b_new    = (const float*)d_in[13];
    const float* w_ih     = (const float*)d_in[14];
    const float* w_hh     = (const float*)d_in[15];
    const float* b_ih     = (const float*)d_in[16];
    const float* b_hh     = (const float*)d_in[17];
    const float* W_pre    = (const float*)d_in[18];
    const float* b_pre    = (const float*)d_in[19];
    const float* W_out    = (const float*)d_in[20];
    const float* b_out    = (const float*)d_in[21];

    float* out        = (float*)d_out;
    float* out_logp   = out;                       // 16*32000
    float* out_hidden = out + 512000;              // 1*16*96
    float* out_ctx2   = out + 513536;              // 16*96
    float* out_aw2    = out + 515072;              // 16*64
    float* out_cov2   = out + 516096;              // 16*64

    int smem_k1 = (32 * 192) * 4 + 2 * (32 * 96) * 8;   // 24576 + 49152 = 73728
    cudaFuncSetAttribute(enc_feat_kernel, cudaFuncAttributeMaxDynamicSharedMemorySize, smem_k1);
    cudaFuncSetAttribute(decoder_fused_kernel, cudaFuncAttributeMaxDynamicSharedMemorySize, 25600 * 4);
    cudaFuncSetAttribute(logits_kernel, cudaFuncAttributeMaxDynamicSharedMemorySize, 128 * 97 * 4);

    // K1: enc_feat partials (o-quad blocks, R7 inner loop)
    enc_feat_kernel<<<dim3(256, 2), 128, smem_k1>>>(enc, attn_w, attn_b);
    // K2: fused attn1 + GRU + attn2 + outproj
    decoder_fused_kernel<<<16, 1024, 25600 * 4>>>(
        enc, ids, hidden, coverage, emb, W_dec, b_dec, cvg_w, cvg_b, v,
        W_new, b_new, w_ih, w_hh, b_ih, b_hh, W_pre, b_pre,
        out_hidden, out_ctx2, out_aw2, out_cov2);
    // K3: logits (coalesced smem-staged f32x2) + b-major sumexp partials
    logits_kernel<<<250, 128, 128 * 97 * 4>>>(W_out, b_out, out_logp);
    // K4: overlapped logZ + in-place normalize
    finalize_kernel<<<dim3(32, 16), 256>>>(out_logp);
}

// round 16
// speedup vs baseline: 1.3313x; 1.1028x over previous
#include <cuda_runtime.h>
#include <math.h>

#define BATCH 16
#define ENCN  64
#define HDIM  96
#define EDIM  128
#define VOC   32000

typedef unsigned long long u64;

__device__ __forceinline__ u64 pack2(float x) {
    u64 r;
    asm("mov.b64 %0, {%1, %1};" : "=l"(r) : "r"(__float_as_uint(x)));
    return r;
}
__device__ __forceinline__ u64 fma2(u64 a, u64 b, u64 c) {
    u64 d;
    asm("fma.rn.f32x2 %0, %1, %2, %3;" : "=l"(d) : "l"(a), "l"(b), "l"(c));
    return d;
}
__device__ __forceinline__ void unpack2(u64 v, float& lo, float& hi) {
    unsigned int l, h;
    asm("mov.b64 {%0, %1}, %2;" : "=r"(l), "=r"(h) : "l"(v));
    lo = __uint_as_float(l);
    hi = __uint_as_float(h);
}

// ---------------- scratch ----------------
__device__ float g_ef0[BATCH * ENCN * HDIM];   // enc_feat partial (i 0..31, +bias)
__device__ float g_ef1[BATCH * ENCN * HDIM];   // enc_feat partial (i 32..63)
__device__ float g_o[BATCH * HDIM];
__device__ float g_psum[BATCH * 256];          // [b][block]

// =====================================================================
// K1: enc_feat partials. grid (512, 2): x = b*32 + o-pair, y = i-half.
// 128 threads = 16 i-groups (2 ch) x 8 w-threads; 12-wide register
// blocking: one K LDS.64 + one E pack per 12 fma.rn.f32x2.
// FROZEN: measured-best of 6 variants (12-wide halves, 48KB smem).
// =====================================================================
extern __shared__ float smem1[];

__global__ void enc_feat_kernel(const float* __restrict__ enc,
                                const float* __restrict__ attn_w,
                                const float* __restrict__ attn_b) {
    int b    = blockIdx.x >> 5;
    int gp   = blockIdx.x & 31;
    int half = blockIdx.y;
    int o0   = gp * 2;
    int i0   = half * 32;

    float* sE = smem1;                        // 32 * 192 floats
    u64*   sK = (u64*)(smem1 + 32 * 192);     // 32 * 96 packed (k_o0, k_o1)
    int tid = threadIdx.x;          // 128

    float4* sE4 = (float4*)sE;
    for (int i = tid; i < 32 * 192 / 4; i += 128) sE4[i] = make_float4(0.f, 0.f, 0.f, 0.f);
    __syncthreads();

    const float* eb = enc + (b * ENCN + i0) * HDIM;
    for (int idx = tid; idx < 32 * HDIM; idx += 128) {
        int i = idx / 96;
        int x = idx - i * 96;
        sE[i * 192 + 47 + x] = eb[idx];
    }
    const float* k0 = attn_w + (size_t)o0 * 589824 + (size_t)i0 * 9216 + 4512;
    const float* k1 = k0 + 589824;
    for (int idx = tid; idx < 32 * 96; idx += 128) {
        int i = idx / 96;
        int d = idx - i * 96;
        float2 kk = make_float2(k0[i * 9216 + d], k1[i * 9216 + d]);
        sK[idx] = *(u64*)&kk;
    }
    __syncthreads();

    int ig = tid >> 3;      // 0..15, 2 channels each
    int wt = tid & 7;       // 0..7
    int w0 = wt * 12;

    u64 acc[12];
#pragma unroll
    for (int j = 0; j < 12; j++) acc[j] = 0ull;

#pragma unroll 1
    for (int i = ig * 2; i < ig * 2 + 2; i++) {
        const float* Er = sE + i * 192 + w0;
        const u64*   Kr = sK + i * 96;
        u64 ep[12];
#pragma unroll
        for (int j = 0; j < 12; j++) ep[j] = pack2(Er[j]);
#pragma unroll 1
        for (int d = 0; d < 96; d += 12) {
#pragma unroll
            for (int u = 0; u < 12; u++) {
                u64 k2 = Kr[d + u];
#pragma unroll
                for (int j = 0; j < 12; j++) {
                    acc[j] = fma2(ep[(u + j) % 12], k2, acc[j]);  // static idx after unroll
                }
                ep[u] = pack2(Er[d + u + 12]);   // slide (max idx 6143, in-bounds)
            }
        }
    }

    float a0[12], a1[12];
#pragma unroll
    for (int j = 0; j < 12; j++) unpack2(acc[j], a0[j], a1[j]);

    // reduce the 16 i-groups (tree over tid strides 64,32,16,8)
    __syncthreads();
    float* red = smem1;     // reuse (128 * 24 floats = 12 KB)
#pragma unroll
    for (int j = 0; j < 12; j++) {
        red[tid * 24 + j]      = a0[j];
        red[tid * 24 + 12 + j] = a1[j];
    }
    __syncthreads();
    for (int s = 64; s >= 8; s >>= 1) {
        if (tid < s) {
#pragma unroll
            for (int j = 0; j < 24; j++) red[tid * 24 + j] += red[(tid + s) * 24 + j];
        }
        __syncthreads();
    }
    if (tid < 8) {
        float* dst = half ? g_ef1 : g_ef0;
        float bb0 = half ? 0.f : attn_b[o0];
        float bb1 = half ? 0.f : attn_b[o0 + 1];
#pragma unroll
        for (int j = 0; j < 12; j++) {
            dst[(b * ENCN + o0) * 96 + tid * 12 + j]     = red[tid * 24 + j] + bb0;
            dst[(b * ENCN + o0 + 1) * 96 + tid * 12 + j] = red[tid * 24 + 12 + j] + bb1;
        }
    }
}

// =====================================================================
// K2: fully fused per-batch decoder: attn1 -> GRU -> attn2 -> outproj.
// grid=16 (one block per batch), block=1024 (32 warps).
// =====================================================================
extern __shared__ float smem2[];

__global__ void decoder_fused_kernel(const float* __restrict__ enc,
                                     const int* __restrict__ ids,
                                     const float* __restrict__ hidden,
                                     const float* __restrict__ coverage,
                                     const float* __restrict__ emb,
                                     const float* __restrict__ W_dec,
                                     const float* __restrict__ b_dec,
                                     const float* __restrict__ cvg_w,
                                     const float* __restrict__ cvg_b,
                                     const float* __restrict__ v,
                                     const float* __restrict__ W_new,
                                     const float* __restrict__ b_new,
                                     const float* __restrict__ w_ih,
                                     const float* __restrict__ w_hh,
                                     const float* __restrict__ b_ih,
                                     const float* __restrict__ b_hh,
                                     const float* __restrict__ W_pre,
                                     const float* __restrict__ b_pre,
                                     float* __restrict__ out_hidden,
                                     float* __restrict__ out_ctx2,
                                     float* __restrict__ out_aw2,
                                     float* __restrict__ out_cov2) {
    int b    = blockIdx.x;
    int t    = threadIdx.x;     // 1024
    int warp = t >> 5;
    int lane = t & 31;

    float* sWdec = smem2;               // 9216
    float* sC    = sWdec + 9216;        // 4096   C[e][i] = cvg_w[e,i,0,47]
    float* sEnc  = sC + 4096;           // 6144   enc[b]
    float* sEf   = sEnc + 6144;         // 6144   encfeat[b]

    __shared__ float sh[96], sv[96], scov[64], sdec[96], scvg[64], ss[64],
                     saw[64], sred[64], sctx[96], scat[224], sx[96],
                     sgi[288], sgh[288], shnew[96], so2[192];

    for (int i = t; i < 9216; i += 1024) sWdec[i] = W_dec[i];
    for (int i = t; i < 4096; i += 1024) {
        int e = i >> 6, ii = i & 63;
        sC[i] = cvg_w[e * 6144 + ii * 96 + 47];
    }
    for (int i = t; i < 6144; i += 1024) {
        sEnc[i] = enc[b * 6144 + i];
        sEf[i]  = g_ef0[b * 6144 + i] + g_ef1[b * 6144 + i];
    }
    if (t < 96) { sh[t] = hidden[b * 96 + t]; sv[t] = v[b * 96 + t]; }
    if (t < 64) scov[t] = coverage[b * 64 + t];
    __syncthreads();

    // =========== PHASE A: attention #1 ===========
#pragma unroll
    for (int k = 0; k < 3; k++) {
        int h = warp * 3 + k;
        const float* wr = sWdec + h * 96;
        float a = sh[lane] * wr[lane];
        a = fmaf(sh[lane + 32], wr[lane + 32], a);
        a = fmaf(sh[lane + 64], wr[lane + 64], a);
#pragma unroll
        for (int s = 16; s > 0; s >>= 1) a += __shfl_down_sync(0xffffffffu, a, s);
        if (lane == 0) sdec[h] = a + b_dec[h];
    }
#pragma unroll
    for (int k = 0; k < 2; k++) {
        int e = warp * 2 + k;
        const float* cw = sC + e * 64;
        float c = scov[lane] * cw[lane];
        c = fmaf(scov[lane + 32], cw[lane + 32], c);
#pragma unroll
        for (int s = 16; s > 0; s >>= 1) c += __shfl_down_sync(0xffffffffu, c, s);
        if (lane == 0) scvg[e] = c + cvg_b[e];
    }
    __syncthreads();

#pragma unroll
    for (int k = 0; k < 2; k++) {
        int e = warp * 2 + k;
        const float* ef = sEf + e * 96;
        float cg = scvg[e];
        float a = 0.f;
#pragma unroll
        for (int q = 0; q < 3; q++) {
            int h = lane + 32 * q;
            a = fmaf(tanhf(ef[h] + sdec[h] + cg), sv[h], a);
        }
#pragma unroll
        for (int s = 16; s > 0; s >>= 1) a += __shfl_down_sync(0xffffffffu, a, s);
        if (lane == 0) ss[e] = a;
    }
    __syncthreads();

    float ex = 0.f;
    if (t < 64) {
        float m = -1e30f;
#pragma unroll
        for (int e = 0; e < 64; e++) m = fmaxf(m, ss[e]);
        ex = expf(ss[t] - m);
        sred[t] = ex;
    }
    __syncthreads();
    for (int s = 32; s >= 1; s >>= 1) {
        if (t < s) sred[t] += sred[t + s];
        __syncthreads();
    }
    {
        float invZ = 1.0f / sred[0];
        if (t < 64) {
            float aw = ex * invZ;
            saw[t] = aw;
            scov[t] = scov[t] + aw;
        }
    }
    __syncthreads();

    if (t < 96) {
        float c = 0.f;
        const float* ebp = sEnc + t;
#pragma unroll 8
        for (int e = 0; e < 64; e++) c = fmaf(saw[e], ebp[e * 96], c);
        sctx[t] = c;
    }
    __syncthreads();

    // =========== GRU ===========
    {
        int id = ids[b];
        if (t < 224) scat[t] = (t < 128) ? emb[(size_t)id * 128 + t] : sctx[t - 128];
    }
    __syncthreads();

#pragma unroll
    for (int k = 0; k < 3; k++) {
        int h = warp * 3 + k;
        const float* wr = W_new + h * 224;
        float a = 0.f;
#pragma unroll
        for (int q = 0; q < 7; q++) {
            int j = lane + 32 * q;
            a = fmaf(scat[j], wr[j], a);
        }
#pragma unroll
        for (int s = 16; s > 0; s >>= 1) a += __shfl_down_sync(0xffffffffu, a, s);
        if (lane == 0) sx[h] = a + b_new[h];
    }
    __syncthreads();

#pragma unroll
    for (int k = 0; k < 18; k++) {
        int r = k * 32 + warp;
        bool is_gi = r < 288;
        int rr = is_gi ? r : r - 288;
        const float* wr  = (is_gi ? w_ih : w_hh) + rr * 96;
        const float* vec = is_gi ? sx : sh;
        float a = vec[lane] * wr[lane];
        a = fmaf(vec[lane + 32], wr[lane + 32], a);
        a = fmaf(vec[lane + 64], wr[lane + 64], a);
#pragma unroll
        for (int s = 16; s > 0; s >>= 1) a += __shfl_down_sync(0xffffffffu, a, s);
        if (lane == 0) {
            if (is_gi) sgi[rr] = a + b_ih[rr];
            else       sgh[rr] = a + b_hh[rr];
        }
    }
    __syncthreads();

    if (t < 96) {
        float r = 1.0f / (1.0f + expf(-(sgi[t] + sgh[t])));
        float z = 1.0f / (1.0f + expf(-(sgi[96 + t] + sgh[96 + t])));
        float n = tanhf(sgi[192 + t] + r * sgh[192 + t]);
        float hn = (1.0f - z) * n + z * sh[t];
        shnew[t] = hn;
        out_hidden[b * 96 + t] = hn;
    }
    __syncthreads();

    // =========== PHASE B: attention #2 ===========
#pragma unroll
    for (int k = 0; k < 3; k++) {
        int h = warp * 3 + k;
        const float* wr = sWdec + h * 96;
        float a = shnew[lane] * wr[lane];
        a = fmaf(shnew[lane + 32], wr[lane + 32], a);
        a = fmaf(shnew[lane + 64], wr[lane + 64], a);
#pragma unroll
        for (int s = 16; s > 0; s >>= 1) a += __shfl_down_sync(0xffffffffu, a, s);
        if (lane == 0) sdec[h] = a + b_dec[h];
    }
#pragma unroll
    for (int k = 0; k < 2; k++) {
        int e = warp * 2 + k;
        const float* cw = sC + e * 64;
        float c = scov[lane] * cw[lane];
        c = fmaf(scov[lane + 32], cw[lane + 32], c);
#pragma unroll
        for (int s = 16; s > 0; s >>= 1) c += __shfl_down_sync(0xffffffffu, c, s);
        if (lane == 0) scvg[e] = c + cvg_b[e];
    }
    __syncthreads();

#pragma unroll
    for (int k = 0; k < 2; k++) {
        int e = warp * 2 + k;
        const float* ef = sEf + e * 96;
        float cg = scvg[e];
        float a = 0.f;
#pragma unroll
        for (int q = 0; q < 3; q++) {
            int h = lane + 32 * q;
            a = fmaf(tanhf(ef[h] + sdec[h] + cg), sv[h], a);
        }
#pragma unroll
        for (int s = 16; s > 0; s >>= 1) a += __shfl_down_sync(0xffffffffu, a, s);
        if (lane == 0) ss[e] = a;
    }
    __syncthreads();

    ex = 0.f;
    if (t < 64) {
        float m = -1e30f;
#pragma unroll
        for (int e = 0; e < 64; e++) m = fmaxf(m, ss[e]);
        ex = expf(ss[t] - m);
        sred[t] = ex;
    }
    __syncthreads();
    for (int s = 32; s >= 1; s >>= 1) {
        if (t < s) sred[t] += sred[t + s];
        __syncthreads();
    }
    {
        float invZ = 1.0f / sred[0];
        if (t < 64) {
            float aw = ex * invZ;
            saw[t] = aw;
            out_aw2[b * 64 + t]  = aw;
            out_cov2[b * 64 + t] = scov[t] + aw;
        }
    }
    __syncthreads();

    if (t < 96) {
        float c = 0.f;
        const float* ebp = sEnc + t;
#pragma unroll 8
        for (int e = 0; e < 64; e++) c = fmaf(saw[e], ebp[e * 96], c);
        out_ctx2[b * 96 + t] = c;
        so2[t]       = shnew[t];
        so2[96 + t]  = c;
    }
    __syncthreads();

    // =========== outproj ===========
#pragma unroll
    for (int k = 0; k < 3; k++) {
        int h = warp * 3 + k;
        const float* wr = W_pre + h * 192;
        float a = 0.f;
#pragma unroll
        for (int q = 0; q < 6; q++) {
            int j = lane + 32 * q;
            a = fmaf(so2[j], wr[j], a);
        }
#pragma unroll
        for (int s = 16; s > 0; s >>= 1) a += __shfl_down_sync(0xffffffffu, a, s);
        if (lane == 0) g_o[b * 96 + h] = tanhf(a + b_pre[h]);
    }
}

// =====================================================================
// K3: logits via f32x2, coalesced smem-staged W.
// 250 blocks x 128 threads; psum stored b-major.
// =====================================================================
extern __shared__ float smem3[];

__global__ void logits_kernel(const float* __restrict__ W_out,
                              const float* __restrict__ b_out,
                              float* __restrict__ out_logp) {
    float* sW = smem3;                               // 128 * 97 (padded)
    __shared__ __align__(16) u64 sO2[96 * 8];        // [k][bpair]
    __shared__ float swred[4][16];
    int t = threadIdx.x;        // 128
    int warp = t >> 5, lane = t & 31;
    int v0 = blockIdx.x * 128;

    {
        const float4* src = (const float4*)(W_out + (size_t)v0 * 96);
        for (int idx = t; idx < 128 * 24; idx += 128) {
            int r = idx / 24;
            int k4 = idx - r * 24;
            float4 w4 = src[r * 24 + k4];
            float* dst = sW + r * 97 + k4 * 4;
            dst[0] = w4.x; dst[1] = w4.y; dst[2] = w4.z; dst[3] = w4.w;
        }
    }
    for (int idx = t; idx < 96 * 8; idx += 128) {
        int k = idx >> 3, q = idx & 7;
        float2 oo = make_float2(g_o[(2 * q) * 96 + k], g_o[(2 * q + 1) * 96 + k]);
        sO2[idx] = *(u64*)&oo;
    }
    __syncthreads();

    u64 acc2[8] = {0ull, 0ull, 0ull, 0ull, 0ull, 0ull, 0ull, 0ull};
    const float* wr = sW + t * 97;
#pragma unroll 4
    for (int k = 0; k < 96; k++) {
        u64 wp = pack2(wr[k]);
        const u64* o2 = sO2 + k * 8;
#pragma unroll
        for (int q = 0; q < 8; q++) acc2[q] = fma2(wp, o2[q], acc2[q]);
    }

    float acc[16];
#pragma unroll
    for (int q = 0; q < 8; q++) unpack2(acc2[q], acc[2 * q], acc[2 * q + 1]);

    float bo = b_out[v0 + t];
#pragma unroll
    for (int bb = 0; bb < 16; bb++) {
        acc[bb] += bo;
        out_logp[bb * VOC + v0 + t] = acc[bb];
        acc[bb] = expf(acc[bb]);
    }
#pragma unroll
    for (int bb = 0; bb < 16; bb++) {
#pragma unroll
        for (int s = 16; s > 0; s >>= 1) acc[bb] += __shfl_down_sync(0xffffffffu, acc[bb], s);
    }
    if (lane == 0) {
#pragma unroll
        for (int bb = 0; bb < 16; bb++) swred[warp][bb] = acc[bb];
    }
    __syncthreads();
    if (t < 16) {
        float s = swred[0][t] + swred[1][t] + swred[2][t] + swred[3][t];
        g_psum[t * 256 + blockIdx.x] = s;       // b-major
    }
}

// =====================================================================
// K4: finalize. Payload float4 loaded FIRST (overlaps logZ latency),
// then per-warp coalesced logZ (contiguous psum reads + xor-shfl),
// subtract, store. grid (32, 16), block 256.
// =====================================================================
__global__ void finalize_kernel(float* __restrict__ out_logp) {
    int b = blockIdx.y;
    int t = threadIdx.x;        // 256
    int lane = t & 31;

    // start payload load immediately (250 float4 per block)
    float4* p = (float4*)(out_logp + (size_t)b * VOC) + blockIdx.x * 250;
    bool act = t < 250;
    float4 v = make_float4(0.f, 0.f, 0.f, 0.f);
    if (act) v = p[t];

    // logZ: coalesced reads of 250 b-major psums, fixed-order lane sums
    float s = 0.f;
    const float* ps = g_psum + b * 256;
#pragma unroll
    for (int q = 0; q < 8; q++) {
        int idx = q * 32 + lane;
        if (idx < 250) s += ps[idx];
    }
#pragma unroll
    for (int k = 16; k > 0; k >>= 1) s += __shfl_xor_sync(0xffffffffu, s, k);
    float lz = logf(s);

    if (act) {
        v.x -= lz; v.y -= lz; v.z -= lz; v.w -= lz;
        p[t] = v;
    }
}

// =====================================================================
extern "C" void kernel_launch(void* const* d_in, const int* in_sizes, int n_in,
                              void* d_out, int out_size) {
    const float* enc      = (const float*)d_in[0];
    const int*   ids      = (const int*)d_in[1];
    const float* hidden   = (const float*)d_in[2];
    const float* coverage = (const float*)d_in[3];
    const float* emb      = (const float*)d_in[4];
    const float* W_dec    = (const float*)d_in[5];
    const float* b_dec    = (const float*)d_in[6];
    const float* attn_w   = (const float*)d_in[7];
    const float* attn_b   = (const float*)d_in[8];
    const float* cvg_w    = (const float*)d_in[9];
    const float* cvg_b    = (const float*)d_in[10];
    const float* v        = (const float*)d_in[11];
    const float* W_new    = (const float*)d_in[12];
    const float* b_new    = (const float*)d_in[13];
    const float* w_ih     = (const float*)d_in[14];
    const float* w_hh     = (const float*)d_in[15];
    const float* b_ih     = (const float*)d_in[16];
    const float* b_hh     = (const float*)d_in[17];
    const float* W_pre    = (const float*)d_in[18];
    const float* b_pre    = (const float*)d_in[19];
    const float* W_out    = (const float*)d_in[20];
    const float* b_out    = (const float*)d_in[21];

    float* out        = (float*)d_out;
    float* out_logp   = out;                       // 16*32000
    float* out_hidden = out + 512000;              // 1*16*96
    float* out_ctx2   = out + 513536;              // 16*96
    float* out_aw2    = out + 515072;              // 16*64
    float* out_cov2   = out + 516096;              // 16*64

    cudaFuncSetAttribute(enc_feat_kernel, cudaFuncAttributeMaxDynamicSharedMemorySize, 49152);
    cudaFuncSetAttribute(decoder_fused_kernel, cudaFuncAttributeMaxDynamicSharedMemorySize, 25600 * 4);
    cudaFuncSetAttribute(logits_kernel, cudaFuncAttributeMaxDynamicSharedMemorySize, 128 * 97 * 4);

    // K1: enc_feat partials (12-wide register blocking — FROZEN best config)
    enc_feat_kernel<<<dim3(512, 2), 128, 49152>>>(enc, attn_w, attn_b);
    // K2: fused attn1 + GRU + attn2 + outproj
    decoder_fused_kernel<<<16, 1024, 25600 * 4>>>(
        enc, ids, hidden, coverage, emb, W_dec, b_dec, cvg_w, cvg_b, v,
        W_new, b_new, w_ih, w_hh, b_ih, b_hh, W_pre, b_pre,
        out_hidden, out_ctx2, out_aw2, out_cov2);
    // K3: logits (coalesced smem-staged f32x2) + b-major sumexp partials
    logits_kernel<<<250, 128, 128 * 97 * 4>>>(W_out, b_out, out_logp);
    // K4: overlapped logZ + in-place normalize
    finalize_kernel<<<dim3(32, 16), 256>>>(out_logp);
}